// round 12
// baseline (speedup 1.0000x reference)
#include <cuda_runtime.h>
#include <cuda_fp16.h>
#include <math.h>
#include <stdint.h>

// Problem constants
#define BATCH   65536
#define NNODES  2
#define FIN     256
#define KDIM    1024
#define MROWS   131072
#define SLOPE   0.2f

// GEMM tiling
#define BM 128
#define BN 128
#define BK 64
#define NKITER 16               // 1024 / 64

// SMEM layout (bytes)
#define COEF   0                // 128 rows * 8 f32 = 4096
#define AOFF   4096             // A bufs: 2 * 36864 (hi 18432 + lo 18432)
#define ABUF   36864
#define SPLITO 18432            // lo offset within an A buf
#define BOFF   77824            // B bufs: 2 * 18432 (single fp16)
#define BBUF   18432
#define SMEM_TOTAL 114688
#define PITCH  144              // 64 fp16 = 128B data + 16B pad

#define NTHREADS 320            // warps 0-7 consumers, warps 8-9 producers
#define NWARPS   10

// Scratch: Wstack^T fp16, chunk-major [kc 0..15][n 0..255][64 fp16]
__device__ float g_wst[FIN * 8];
__device__ __half g_Wh[16 * 256 * 64];

__device__ __forceinline__ uint32_t smem_u32(const void* p) {
    uint32_t a;
    asm("{ .reg .u64 t; cvta.to.shared.u64 t, %1; cvt.u32.u64 %0, t; }" : "=r"(a) : "l"(p));
    return a;
}
__device__ __forceinline__ void ldsm_x4(uint32_t* r, uint32_t addr) {
    asm volatile("ldmatrix.sync.aligned.m8n8.x4.shared.b16 {%0,%1,%2,%3}, [%4];"
        : "=r"(r[0]), "=r"(r[1]), "=r"(r[2]), "=r"(r[3]) : "r"(addr));
}
__device__ __forceinline__ void ldsm_x2(uint32_t* r, uint32_t addr) {
    asm volatile("ldmatrix.sync.aligned.m8n8.x2.shared.b16 {%0,%1}, [%2];"
        : "=r"(r[0]), "=r"(r[1]) : "r"(addr));
}
// f32-accumulator MMA (main term)
__device__ __forceinline__ void mma_fp16(float* d, const uint32_t* a, const uint32_t* b) {
    asm volatile("mma.sync.aligned.m16n8k16.row.col.f32.f16.f16.f32 "
        "{%0,%1,%2,%3}, {%4,%5,%6,%7}, {%8,%9}, {%0,%1,%2,%3};"
        : "+f"(d[0]), "+f"(d[1]), "+f"(d[2]), "+f"(d[3])
        : "r"(a[0]), "r"(a[1]), "r"(a[2]), "r"(a[3]), "r"(b[0]), "r"(b[1]));
}
// f16-accumulator MMA (lo correction term)
__device__ __forceinline__ void mma_fp16h(uint32_t* d, const uint32_t* a, const uint32_t* b) {
    asm volatile("mma.sync.aligned.m16n8k16.row.col.f16.f16.f16.f16 "
        "{%0,%1}, {%2,%3,%4,%5}, {%6,%7}, {%0,%1};"
        : "+r"(d[0]), "+r"(d[1])
        : "r"(a[0]), "r"(a[1]), "r"(a[2]), "r"(a[3]), "r"(b[0]), "r"(b[1]));
}
__device__ __forceinline__ void cp_async16(uint32_t daddr, const void* src) {
    asm volatile("cp.async.cg.shared.global [%0], [%1], 16;"
        :: "r"(daddr), "l"(src) : "memory");
}
__device__ __forceinline__ void cp_async_wait_all() {
    asm volatile("cp.async.wait_all;" ::: "memory");
}

// ---------------------------------------------------------------------------
// Kernel 1: wst dot products. One warp per output, 2048 outputs.
// ---------------------------------------------------------------------------
__global__ void gat_prep(const float* __restrict__ W, const float* __restrict__ a) {
    int wid = threadIdx.x >> 5, lane = threadIdx.x & 31;
    int t = blockIdx.x * 8 + wid;
    int f = t >> 3, c = t & 7, hd = c & 3, tg = c >> 2;
    const float4* wrow = (const float4*)(W + f * KDIM + hd * 256);
    const float4* av   = (const float4*)(a + hd * 512 + tg * 256);
    float s = 0.f;
#pragma unroll
    for (int q = 0; q < 2; ++q) {
        int i = lane + q * 32;
        float4 w4 = wrow[i], a4 = av[i];
        s += w4.x * a4.x + w4.y * a4.y + w4.z * a4.z + w4.w * a4.w;
    }
#pragma unroll
    for (int off = 16; off > 0; off >>= 1) s += __shfl_xor_sync(0xFFFFFFFFu, s, off);
    if (lane == 0) g_wst[t] = s;
}

// ---------------------------------------------------------------------------
// Kernel 1b: Wstack^T as single fp16, 64-wide chunk-major layout.
// ---------------------------------------------------------------------------
__global__ void gat_prepB(const float* __restrict__ W) {
    int idx = blockIdx.x * 256 + threadIdx.x;        // n*1024 + k
    int n = idx >> 10, k = idx & 1023;
    float w = W[(k & 255) * KDIM + (k >> 8) * 256 + n];
    g_Wh[(k >> 6) * 16384 + n * 64 + (k & 63)] = __float2half_rn(w);
}

// ---------------------------------------------------------------------------
// Kernel 2: warp-specialized GEMM (fp16 hi f32-acc + fp16 lo f16-acc).
// ---------------------------------------------------------------------------
__device__ __forceinline__ float lrelu(float x) { return x > 0.f ? x : SLOPE * x; }

__device__ __forceinline__ void produce_chunk(
    char* smem, uint32_t sb, int c, int t, int n0g, int m0,
    const float* __restrict__ h)
{
    const int buf = c & 1;

    // ---- B: cp.async GMEM -> SMEM (16 granules per thread) ----
    {
        const uint32_t dbase = sb + BOFF + buf * BBUF;
        const char* srcH = (const char*)g_Wh + c * 32768 + n0g * 128;
#pragma unroll
        for (int g2 = 0; g2 < 16; ++g2) {
            int unit = t + 64 * g2;                  // 0..1023
            int n = unit >> 3, j = unit & 7;
            cp_async16(dbase + n * PITCH + j * 16, srcH + n * 128 + j * 16);
        }
    }

    // ---- A: build 64 k-values for rows t and t+64 ----
    const int hd = c >> 2;
    const int fo = (c & 3) * 64;
#pragma unroll
    for (int rr = 0; rr < 2; ++rr) {
        const int r = t + rr * 64;
        const float* hp0 = h + (size_t)(((m0 + r) >> 1)) * 512;
        const float* hp1 = hp0 + 256;
        float2 cc = ((const float2*)(smem + COEF + r * 32))[hd];
        const float4* q0 = (const float4*)(hp0 + fo);
        const float4* q1 = (const float4*)(hp1 + fo);
        char* awh = smem + AOFF + buf * ABUF + r * PITCH;
        char* awl = awh + SPLITO;
#pragma unroll
        for (int s8 = 0; s8 < 8; ++s8) {             // strips of 8 floats
            float4 a0 = q0[s8 * 2], a1 = q0[s8 * 2 + 1];
            float4 b0 = q1[s8 * 2], b1 = q1[s8 * 2 + 1];
            float x0 = cc.x * a0.x + cc.y * b0.x, x1 = cc.x * a0.y + cc.y * b0.y;
            float x2 = cc.x * a0.z + cc.y * b0.z, x3 = cc.x * a0.w + cc.y * b0.w;
            float x4 = cc.x * a1.x + cc.y * b1.x, x5 = cc.x * a1.y + cc.y * b1.y;
            float x6 = cc.x * a1.z + cc.y * b1.z, x7 = cc.x * a1.w + cc.y * b1.w;
            __half2 h01 = __floats2half2_rn(x0, x1);
            __half2 h23 = __floats2half2_rn(x2, x3);
            __half2 h45 = __floats2half2_rn(x4, x5);
            __half2 h67 = __floats2half2_rn(x6, x7);
            __half2 l01 = __floats2half2_rn(x0 - __low2float(h01), x1 - __high2float(h01));
            __half2 l23 = __floats2half2_rn(x2 - __low2float(h23), x3 - __high2float(h23));
            __half2 l45 = __floats2half2_rn(x4 - __low2float(h45), x5 - __high2float(h45));
            __half2 l67 = __floats2half2_rn(x6 - __low2float(h67), x7 - __high2float(h67));
            uint4 hv, lv;
            hv.x = *(uint32_t*)&h01; hv.y = *(uint32_t*)&h23;
            hv.z = *(uint32_t*)&h45; hv.w = *(uint32_t*)&h67;
            lv.x = *(uint32_t*)&l01; lv.y = *(uint32_t*)&l23;
            lv.z = *(uint32_t*)&l45; lv.w = *(uint32_t*)&l67;
            *(uint4*)(awh + s8 * 16) = hv;
            *(uint4*)(awl + s8 * 16) = lv;
        }
    }
    cp_async_wait_all();
}

__global__ void __launch_bounds__(NTHREADS, 1)
gat_main(const float* __restrict__ h, const int* __restrict__ adj,
         float* __restrict__ out) {
    extern __shared__ char smem[];
    const uint32_t sb = smem_u32(smem);
    const int tid = threadIdx.x;
    const int wid = tid >> 5;
    const int lane = tid & 31;
    const int m0 = blockIdx.y * BM;
    const int n0g = blockIdx.x * BN;

    // ---- prologue: fused attention coefficients (warp per graph) ----
    for (int g = wid; g < 64; g += NWARPS) {
        const float* hb = h + (size_t)((m0 >> 1) + g) * 512;
        float p[16];
#pragma unroll
        for (int c = 0; c < 16; ++c) p[c] = 0.f;
#pragma unroll
        for (int q = 0; q < 8; ++q) {
            int f = lane + q * 32;
            float h0 = hb[f];
            float h1 = hb[256 + f];
            const float4* wp = (const float4*)(g_wst + f * 8);
            float4 w0 = wp[0];
            float4 w1 = wp[1];
            p[0] += h0 * w0.x; p[1] += h0 * w0.y; p[2] += h0 * w0.z; p[3] += h0 * w0.w;
            p[4] += h0 * w1.x; p[5] += h0 * w1.y; p[6] += h0 * w1.z; p[7] += h0 * w1.w;
            p[8]  += h1 * w0.x; p[9]  += h1 * w0.y; p[10] += h1 * w0.z; p[11] += h1 * w0.w;
            p[12] += h1 * w1.x; p[13] += h1 * w1.y; p[14] += h1 * w1.z; p[15] += h1 * w1.w;
        }
#pragma unroll
        for (int off = 16; off > 0; off >>= 1) {
#pragma unroll
            for (int c = 0; c < 16; ++c) p[c] += __shfl_xor_sync(0xFFFFFFFFu, p[c], off);
        }
        if (lane == 0) {
            int b = (m0 >> 1) + g;
            int a00 = adj[b * 4 + 0], a01 = adj[b * 4 + 1];
            int a10 = adj[b * 4 + 2], a11 = adj[b * 4 + 3];
            float cf[16];
#pragma unroll
            for (int i = 0; i < 2; ++i) {
                int mk0 = (i == 0) ? a00 : a10;
                int mk1 = (i == 0) ? a01 : a11;
#pragma unroll
                for (int hd = 0; hd < 4; ++hd) {
                    float si = p[i * 8 + hd];
                    float e0 = lrelu(si + p[4 + hd]);
                    float e1 = lrelu(si + p[12 + hd]);
                    float mx = -INFINITY;
                    if (mk0) mx = e0;
                    if (mk1) mx = fmaxf(mx, e1);
                    float x0 = mk0 ? expf(e0 - mx) : 0.f;
                    float x1 = mk1 ? expf(e1 - mx) : 0.f;
                    float inv = 0.25f / (x0 + x1);
                    cf[i * 8 + hd * 2 + 0] = x0 * inv;
                    cf[i * 8 + hd * 2 + 1] = x1 * inv;
                }
            }
            float4* dst = (float4*)(smem + COEF + g * 64);
#pragma unroll
            for (int q = 0; q < 4; ++q) dst[q] = *(float4*)&cf[q * 4];
        }
    }
    __syncthreads();

    if (wid >= 8) {
        // ---------------- PRODUCER (warps 8-9; 64 threads, 2 rows each) ----
        const int t = tid - 256;                     // 0..63
        produce_chunk(smem, sb, 0, t, n0g, m0, h);
        __syncthreads();                             // chunk 0 visible
        for (int c = 0; c < NKITER; ++c) {
            if (c + 1 < NKITER)
                produce_chunk(smem, sb, c + 1, t, n0g, m0, h);
            __syncthreads();                         // chunk c+1 visible / buf c released
        }
    } else {
        // ---------------- CONSUMER (warps 0-7) ----------------
        const int mband = (wid & 3) * 32;
        const int nband = (wid >> 2) * 64;
        const uint32_t aoff_l = (uint32_t)((mband + (lane & 7) + ((lane >> 3) & 1) * 8) * PITCH
                                           + (lane >> 4) * 16);
        const uint32_t boff_l = (uint32_t)((nband + (lane & 7)) * PITCH
                                           + ((lane >> 3) & 1) * 16);
        float    acc[2][8][4];                       // main term, f32
        uint32_t hl[2][8][2];                        // lo term, f16x2 pairs
#pragma unroll
        for (int mt = 0; mt < 2; ++mt)
#pragma unroll
            for (int nt = 0; nt < 8; ++nt) {
#pragma unroll
                for (int e = 0; e < 4; ++e) acc[mt][nt][e] = 0.f;
                hl[mt][nt][0] = 0u; hl[mt][nt][1] = 0u;
            }

        __syncthreads();                             // chunk 0 ready
        for (int c = 0; c < NKITER; ++c) {
            const int s = c & 1;
            const uint32_t ahb = sb + AOFF + s * ABUF + aoff_l;
            const uint32_t alb = ahb + SPLITO;
            const uint32_t bbb = sb + BOFF + s * BBUF + boff_l;
#pragma unroll
            for (int ks = 0; ks < 4; ++ks) {         // k16 slices
                uint32_t ah[2][4], al[2][4], bq[8][2];
                ldsm_x4(ah[0], ahb + ks * 32);
                ldsm_x4(ah[1], ahb + 16 * PITCH + ks * 32);
                ldsm_x4(al[0], alb + ks * 32);
                ldsm_x4(al[1], alb + 16 * PITCH + ks * 32);
#pragma unroll
                for (int nt = 0; nt < 8; ++nt)
                    ldsm_x2(bq[nt], bbb + nt * 8 * PITCH + ks * 32);

                // term-major: dependent MMAs on one accumulator are 16 apart
#pragma unroll
                for (int mt = 0; mt < 2; ++mt)
#pragma unroll
                    for (int nt = 0; nt < 8; ++nt)
                        mma_fp16(acc[mt][nt], ah[mt], bq[nt]);     // Ahi*B (f32 acc)
#pragma unroll
                for (int mt = 0; mt < 2; ++mt)
#pragma unroll
                    for (int nt = 0; nt < 8; ++nt)
                        mma_fp16h(hl[mt][nt], al[mt], bq[nt]);     // Alo*B (f16 acc)
            }
            __syncthreads();                         // next chunk ready / buf released
        }

        // ---- epilogue: combine main + lo ----
        const int grow = m0 + mband + (lane >> 2);
        const int gcol = n0g + nband + (lane & 3) * 2;
#pragma unroll
        for (int mt = 0; mt < 2; ++mt) {
#pragma unroll
            for (int nt = 0; nt < 8; ++nt) {
                __half2 lo01 = *(__half2*)&hl[mt][nt][0];
                __half2 lo23 = *(__half2*)&hl[mt][nt][1];
                float* p = out + (size_t)(grow + mt * 16) * 256 + gcol + nt * 8;
                *(float2*)p = make_float2(acc[mt][nt][0] + __low2float(lo01),
                                          acc[mt][nt][1] + __high2float(lo01));
                *(float2*)(p + 8 * 256) = make_float2(acc[mt][nt][2] + __low2float(lo23),
                                                      acc[mt][nt][3] + __high2float(lo23));
            }
        }
    }
}

// ---------------------------------------------------------------------------
// Launch
// ---------------------------------------------------------------------------
extern "C" void kernel_launch(void* const* d_in, const int* in_sizes, int n_in,
                              void* d_out, int out_size) {
    const float* h   = (const float*)d_in[0];
    const int*   adj = (const int*)  d_in[1];
    const float* W   = (const float*)d_in[2];
    const float* a   = (const float*)d_in[3];
    float* out = (float*)d_out;

    cudaFuncSetAttribute(gat_main, cudaFuncAttributeMaxDynamicSharedMemorySize, SMEM_TOTAL);

    gat_prep<<<256, 256>>>(W, a);
    gat_prepB<<<1024, 256>>>(W);
    gat_main<<<dim3(2, 1024), NTHREADS, SMEM_TOTAL>>>(h, adj, out);
}

// round 14
// speedup vs baseline: 1.1993x; 1.1993x over previous
#include <cuda_runtime.h>
#include <cuda_fp16.h>
#include <math.h>
#include <stdint.h>

// Problem constants
#define BATCH   65536
#define NNODES  2
#define FIN     256
#define KDIM    1024
#define MROWS   131072
#define SLOPE   0.2f

// GEMM tiling
#define BM 128
#define BN 128
#define BK 64
#define NKITER 16               // 1024 / 64

// SMEM layout (bytes)
#define COEF   0                // 128 rows * 8 f32 = 4096
#define AOFF   4096             // A bufs: 2 * 18432 (single fp16)
#define ABUF   18432
#define BOFF   40960            // B bufs: 2 * 18432 (single fp16)
#define BBUF   18432
#define SMEM_TOTAL 77824
#define PITCH  144              // 64 fp16 = 128B data + 16B pad

#define NTHREADS 384            // warps 0-7 consumers, warps 8-11 producers

// Scratch: Wstack^T fp16, chunk-major [kc 0..15][n 0..255][64 fp16]
__device__ float g_wst[FIN * 8];
__device__ __half g_Wh[16 * 256 * 64];

__device__ __forceinline__ uint32_t smem_u32(const void* p) {
    uint32_t a;
    asm("{ .reg .u64 t; cvta.to.shared.u64 t, %1; cvt.u32.u64 %0, t; }" : "=r"(a) : "l"(p));
    return a;
}
__device__ __forceinline__ void ldsm_x4(uint32_t* r, uint32_t addr) {
    asm volatile("ldmatrix.sync.aligned.m8n8.x4.shared.b16 {%0,%1,%2,%3}, [%4];"
        : "=r"(r[0]), "=r"(r[1]), "=r"(r[2]), "=r"(r[3]) : "r"(addr));
}
__device__ __forceinline__ void mma_fp16(float* d, const uint32_t* a, const uint32_t* b) {
    asm volatile("mma.sync.aligned.m16n8k16.row.col.f32.f16.f16.f32 "
        "{%0,%1,%2,%3}, {%4,%5,%6,%7}, {%8,%9}, {%0,%1,%2,%3};"
        : "+f"(d[0]), "+f"(d[1]), "+f"(d[2]), "+f"(d[3])
        : "r"(a[0]), "r"(a[1]), "r"(a[2]), "r"(a[3]), "r"(b[0]), "r"(b[1]));
}
__device__ __forceinline__ void cp_async16(uint32_t daddr, const void* src) {
    asm volatile("cp.async.cg.shared.global [%0], [%1], 16;"
        :: "r"(daddr), "l"(src) : "memory");
}
__device__ __forceinline__ void cp_async_wait_all() {
    asm volatile("cp.async.wait_all;" ::: "memory");
}

// ---------------------------------------------------------------------------
// Kernel 1: wst dot products. One warp per output, 2048 outputs.
// ---------------------------------------------------------------------------
__global__ void gat_prep(const float* __restrict__ W, const float* __restrict__ a) {
    int wid = threadIdx.x >> 5, lane = threadIdx.x & 31;
    int t = blockIdx.x * 8 + wid;
    int f = t >> 3, c = t & 7, hd = c & 3, tg = c >> 2;
    const float4* wrow = (const float4*)(W + f * KDIM + hd * 256);
    const float4* av   = (const float4*)(a + hd * 512 + tg * 256);
    float s = 0.f;
#pragma unroll
    for (int q = 0; q < 2; ++q) {
        int i = lane + q * 32;
        float4 w4 = wrow[i], a4 = av[i];
        s += w4.x * a4.x + w4.y * a4.y + w4.z * a4.z + w4.w * a4.w;
    }
#pragma unroll
    for (int off = 16; off > 0; off >>= 1) s += __shfl_xor_sync(0xFFFFFFFFu, s, off);
    if (lane == 0) g_wst[t] = s;
}

// ---------------------------------------------------------------------------
// Kernel 1b: Wstack^T as single fp16, 64-wide chunk-major layout.
// Wt[n][k] = W[k&255][(k>>8)*256 + n]; dest = (k>>6)*16384 + n*64 + (k&63)
// ---------------------------------------------------------------------------
__global__ void gat_prepB(const float* __restrict__ W) {
    int idx = blockIdx.x * 256 + threadIdx.x;        // n*1024 + k
    int n = idx >> 10, k = idx & 1023;
    float w = W[(k & 255) * KDIM + (k >> 8) * 256 + n];
    g_Wh[(k >> 6) * 16384 + n * 64 + (k & 63)] = __float2half_rn(w);
}

// ---------------------------------------------------------------------------
// Kernel 2: warp-specialized GEMM (single fp16 x fp16, f32 acc) + fused attn.
// ---------------------------------------------------------------------------
__device__ __forceinline__ float lrelu(float x) { return x > 0.f ? x : SLOPE * x; }

__device__ __forceinline__ void produce_chunk(
    char* smem, uint32_t sb, int c, int r, int n0g,
    const float* hp0, const float* hp1, const float2* coefp)
{
    const int buf = c & 1;

    // ---- B: cp.async GMEM -> SMEM (single fp16, 8 granules/thread) ----
    {
        const uint32_t dbase = sb + BOFF + buf * BBUF;
        const char* srcH = (const char*)g_Wh + c * 32768 + n0g * 128;
#pragma unroll
        for (int g2 = 0; g2 < 8; ++g2) {
            int unit = r + 128 * g2;                 // 0..1023
            int n = unit >> 3, j = unit & 7;
            cp_async16(dbase + n * PITCH + j * 16, srcH + n * 128 + j * 16);
        }
    }

    // ---- A: build 64 k-values for row r, single fp16 ----
    const int hd = c >> 2;
    const int fo = (c & 3) * 64;
    float2 cc = coefp[hd];
    const float4* q0 = (const float4*)(hp0 + fo);
    const float4* q1 = (const float4*)(hp1 + fo);
    char* awh = smem + AOFF + buf * ABUF + r * PITCH;
#pragma unroll
    for (int s8 = 0; s8 < 8; ++s8) {                 // strips of 8 floats
        float4 a0 = q0[s8 * 2], a1 = q0[s8 * 2 + 1];
        float4 b0 = q1[s8 * 2], b1 = q1[s8 * 2 + 1];
        float x0 = cc.x * a0.x + cc.y * b0.x, x1 = cc.x * a0.y + cc.y * b0.y;
        float x2 = cc.x * a0.z + cc.y * b0.z, x3 = cc.x * a0.w + cc.y * b0.w;
        float x4 = cc.x * a1.x + cc.y * b1.x, x5 = cc.x * a1.y + cc.y * b1.y;
        float x6 = cc.x * a1.z + cc.y * b1.z, x7 = cc.x * a1.w + cc.y * b1.w;
        __half2 h01 = __floats2half2_rn(x0, x1);
        __half2 h23 = __floats2half2_rn(x2, x3);
        __half2 h45 = __floats2half2_rn(x4, x5);
        __half2 h67 = __floats2half2_rn(x6, x7);
        uint4 hv;
        hv.x = *(uint32_t*)&h01; hv.y = *(uint32_t*)&h23;
        hv.z = *(uint32_t*)&h45; hv.w = *(uint32_t*)&h67;
        *(uint4*)(awh + s8 * 16) = hv;
    }
    cp_async_wait_all();                             // B granules landed
}

__global__ void __launch_bounds__(NTHREADS, 1)
gat_main(const float* __restrict__ h, const int* __restrict__ adj,
         float* __restrict__ out) {
    extern __shared__ char smem[];
    const uint32_t sb = smem_u32(smem);
    const int tid = threadIdx.x;
    const int wid = tid >> 5;
    const int lane = tid & 31;
    const int m0 = blockIdx.y * BM;
    const int n0g = blockIdx.x * BN;

    // ---- prologue: fused attention coefficients (warp per graph) ----
    for (int g = wid; g < 64; g += 12) {
        const float* hb = h + (size_t)((m0 >> 1) + g) * 512;
        float p[16];
#pragma unroll
        for (int c = 0; c < 16; ++c) p[c] = 0.f;
#pragma unroll
        for (int q = 0; q < 8; ++q) {
            int f = lane + q * 32;
            float h0 = hb[f];
            float h1 = hb[256 + f];
            const float4* wp = (const float4*)(g_wst + f * 8);
            float4 w0 = wp[0];
            float4 w1 = wp[1];
            p[0] += h0 * w0.x; p[1] += h0 * w0.y; p[2] += h0 * w0.z; p[3] += h0 * w0.w;
            p[4] += h0 * w1.x; p[5] += h0 * w1.y; p[6] += h0 * w1.z; p[7] += h0 * w1.w;
            p[8]  += h1 * w0.x; p[9]  += h1 * w0.y; p[10] += h1 * w0.z; p[11] += h1 * w0.w;
            p[12] += h1 * w1.x; p[13] += h1 * w1.y; p[14] += h1 * w1.z; p[15] += h1 * w1.w;
        }
#pragma unroll
        for (int off = 16; off > 0; off >>= 1) {
#pragma unroll
            for (int c = 0; c < 16; ++c) p[c] += __shfl_xor_sync(0xFFFFFFFFu, p[c], off);
        }
        if (lane == 0) {
            int b = (m0 >> 1) + g;
            int a00 = adj[b * 4 + 0], a01 = adj[b * 4 + 1];
            int a10 = adj[b * 4 + 2], a11 = adj[b * 4 + 3];
            float cf[16];
#pragma unroll
            for (int i = 0; i < 2; ++i) {
                int mk0 = (i == 0) ? a00 : a10;
                int mk1 = (i == 0) ? a01 : a11;
#pragma unroll
                for (int hd = 0; hd < 4; ++hd) {
                    float si = p[i * 8 + hd];
                    float e0 = lrelu(si + p[4 + hd]);
                    float e1 = lrelu(si + p[12 + hd]);
                    float mx = -INFINITY;
                    if (mk0) mx = e0;
                    if (mk1) mx = fmaxf(mx, e1);
                    float x0 = mk0 ? expf(e0 - mx) : 0.f;
                    float x1 = mk1 ? expf(e1 - mx) : 0.f;
                    float inv = 0.25f / (x0 + x1);
                    cf[i * 8 + hd * 2 + 0] = x0 * inv;
                    cf[i * 8 + hd * 2 + 1] = x1 * inv;
                }
            }
            float4* dst = (float4*)(smem + COEF + g * 64);
#pragma unroll
            for (int q = 0; q < 4; ++q) dst[q] = *(float4*)&cf[q * 4];
        }
    }
    __syncthreads();

    if (wid >= 8) {
        // ---------------- PRODUCER (warps 8-11; 128 threads, 1 row each) ----
        const int r = tid - 256;                     // 0..127
        const int row = m0 + r;
        const float* hp0 = h + (size_t)(row >> 1) * 512;
        const float* hp1 = hp0 + 256;
        const float2* coefp = (const float2*)(smem + COEF + r * 32);

        produce_chunk(smem, sb, 0, r, n0g, hp0, hp1, coefp);
        __syncthreads();                             // chunk 0 visible
        for (int c = 0; c < NKITER; ++c) {
            if (c + 1 < NKITER)
                produce_chunk(smem, sb, c + 1, r, n0g, hp0, hp1, coefp);
            __syncthreads();                         // chunk c+1 visible / buf c released
        }
    } else {
        // ---------------- CONSUMER (warps 0-7) ----------------
        const int mband = (wid & 3) * 32;
        const int nband = (wid >> 2) * 64;
        const uint32_t aoff_l = (uint32_t)((mband + (lane & 7) + ((lane >> 3) & 1) * 8) * PITCH
                                           + (lane >> 4) * 16);
        // B x4 covers n8 x k32: lane groups 0-7/8-15/16-23/24-31 -> k0-7/8-15/16-23/24-31
        const uint32_t boff_l = (uint32_t)((nband + (lane & 7)) * PITCH + (lane >> 3) * 16);
        float acc[2][8][4];
#pragma unroll
        for (int mt = 0; mt < 2; ++mt)
#pragma unroll
            for (int nt = 0; nt < 8; ++nt)
#pragma unroll
                for (int e = 0; e < 4; ++e) acc[mt][nt][e] = 0.f;

        __syncthreads();                             // chunk 0 ready
        for (int c = 0; c < NKITER; ++c) {
            const int s = c & 1;
            const uint32_t ahb = sb + AOFF + s * ABUF + aoff_l;
            const uint32_t bbb = sb + BOFF + s * BBUF + boff_l;
#pragma unroll
            for (int kg = 0; kg < 2; ++kg) {         // k32 groups
                uint32_t bb[8][4];
#pragma unroll
                for (int nt = 0; nt < 8; ++nt)
                    ldsm_x4(bb[nt], bbb + nt * 8 * PITCH + kg * 64);
#pragma unroll
                for (int sh = 0; sh < 2; ++sh) {     // k16 sub-slices
                    const int ks = kg * 2 + sh;
                    uint32_t ah[2][4];
                    ldsm_x4(ah[0], ahb + ks * 32);
                    ldsm_x4(ah[1], ahb + 16 * PITCH + ks * 32);
                    // 16 independent accumulators between same-acc MMAs
#pragma unroll
                    for (int mt = 0; mt < 2; ++mt)
#pragma unroll
                        for (int nt = 0; nt < 8; ++nt)
                            mma_fp16(acc[mt][nt], ah[mt], bb[nt] + 2 * sh);
                }
            }
            __syncthreads();                         // next chunk ready / buf released
        }

        // ---- epilogue ----
        const int grow = m0 + mband + (lane >> 2);
        const int gcol = n0g + nband + (lane & 3) * 2;
#pragma unroll
        for (int mt = 0; mt < 2; ++mt) {
#pragma unroll
            for (int nt = 0; nt < 8; ++nt) {
                float* p = out + (size_t)(grow + mt * 16) * 256 + gcol + nt * 8;
                *(float2*)p = make_float2(acc[mt][nt][0], acc[mt][nt][1]);
                *(float2*)(p + 8 * 256) = make_float2(acc[mt][nt][2], acc[mt][nt][3]);
            }
        }
    }
}

// ---------------------------------------------------------------------------
// Launch
// ---------------------------------------------------------------------------
extern "C" void kernel_launch(void* const* d_in, const int* in_sizes, int n_in,
                              void* d_out, int out_size) {
    const float* h   = (const float*)d_in[0];
    const int*   adj = (const int*)  d_in[1];
    const float* W   = (const float*)d_in[2];
    const float* a   = (const float*)d_in[3];
    float* out = (float*)d_out;

    cudaFuncSetAttribute(gat_main, cudaFuncAttributeMaxDynamicSharedMemorySize, SMEM_TOTAL);

    gat_prep<<<256, 256>>>(W, a);
    gat_prepB<<<1024, 256>>>(W);
    gat_main<<<dim3(2, 1024), NTHREADS, SMEM_TOTAL>>>(h, adj, out);
}